// round 5
// baseline (speedup 1.0000x reference)
#include <cuda_runtime.h>
#include <math.h>

#define NB     256
#define NPB    65536
#define NBATCH 4
#define EPS    1e-10f
#define INV_N  (1.0f / 65536.0f)
#define GRID   256           // 64 CTAs per batch
#define CPB    64            // CTAs per batch
#define TPB    256

// ---------- persistent scratch (zero-init at load; re-zeroed every call) ----------
__device__ float  g_joint[NBATCH * NB * NB];   // 1 MB
__device__ float  g_h1[NBATCH * NB];
__device__ float  g_h2[NBATCH * NB];
__device__ double g_sj[NBATCH];
__device__ double g_ej[NBATCH];
__device__ float  g_H1[NBATCH], g_H2[NBATCH];
__device__ float  g_mi[NBATCH];
__device__ unsigned g_barA[NBATCH];            // per-batch accum barrier
__device__ unsigned g_bar2[NBATCH];            // per-batch slice ticket
__device__ unsigned g_done;                    // batch-finalizer counter

__device__ __forceinline__ float fred256(float v, float* sred) {
#pragma unroll
    for (int o = 16; o; o >>= 1) v += __shfl_xor_sync(0xffffffffu, v, o);
    int wid = threadIdx.x >> 5, lid = threadIdx.x & 31;
    if (lid == 0) sred[wid] = v;
    __syncthreads();
    float r = 0.0f;
    if (threadIdx.x < 32) {
        r = (threadIdx.x < 8) ? sred[threadIdx.x] : 0.0f;
#pragma unroll
        for (int o = 4; o; o >>= 1) r += __shfl_xor_sync(0xffffffffu, r, o);
        if (threadIdx.x == 0) sred[0] = r;
    }
    __syncthreads();
    float out = sred[0];
    __syncthreads();
    return out;
}

__global__ __launch_bounds__(TPB)
void mi_fused_kernel(const float* __restrict__ in1, const float* __restrict__ in2,
                     float* __restrict__ out) {
    __shared__ float sh1[NB];
    __shared__ float sh2[NB];
    __shared__ float sred[8];
    int tid = threadIdx.x;
    int blk = blockIdx.x;
    int b   = blk >> 6;                 // batch (64 CTAs per batch)
    int sub = blk & 63;

    // ---- issue input loads first (overlap with smem zeroing) ----
    int base = blk * 1024;
    float4 a = ((const float4*)(in1 + base))[tid];
    float4 c = ((const float4*)(in2 + base))[tid];

    sh1[tid] = 0.0f;
    sh2[tid] = 0.0f;
    __syncthreads();

    // ================= phase A: sparse KDE accumulation =================
    // sigma=0.1 in bin units: only the two straddling bins carry weight
    // (next bin is <= e^-50 ~ 2e-22 relative).
    float* __restrict__ joint = g_joint + b * NB * NB;
    const float xs1[4] = {a.x, a.y, a.z, a.w};
    const float xs2[4] = {c.x, c.y, c.z, c.w};

#pragma unroll
    for (int k = 0; k < 4; k++) {
        float x1 = xs1[k] * 255.0f;
        float x2 = xs2[k] * 255.0f;
        int i0 = min((int)floorf(x1), NB - 2);
        int j0 = min((int)floorf(x2), NB - 2);
        float f1 = x1 - (float)i0, q1 = 1.0f - f1;
        float f2 = x2 - (float)j0, q2 = 1.0f - f2;
        float wa1 = __expf(-50.0f * f1 * f1);
        float wb1 = __expf(-50.0f * q1 * q1);
        float wa2 = __expf(-50.0f * f2 * f2);
        float wb2 = __expf(-50.0f * q2 * q2);

        atomicAdd(&sh1[i0],     wa1);
        atomicAdd(&sh1[i0 + 1], wb1);
        atomicAdd(&sh2[j0],     wa2);
        atomicAdd(&sh2[j0 + 1], wb2);

        float* row = joint + i0 * NB + j0;
        atomicAdd(row,          wa1 * wa2);
        atomicAdd(row + 1,      wa1 * wb2);
        atomicAdd(row + NB,     wb1 * wa2);
        atomicAdd(row + NB + 1, wb1 * wb2);
    }

    __syncthreads();
    atomicAdd(&g_h1[b * NB + tid], sh1[tid]);
    atomicAdd(&g_h2[b * NB + tid], sh2[tid]);

    // ================= per-batch barrier (64 CTAs), backoff poll =================
    __threadfence();
    __syncthreads();
    if (tid == 0) {
        atomicAdd(&g_barA[b], 1u);
        while (*(volatile unsigned*)&g_barA[b] < (unsigned)CPB) __nanosleep(64);
        __threadfence();
    }
    __syncthreads();

    // ================= phase B: reduce own batch's slice + re-zero =================
    float4* j4 = (float4*)(g_joint + b * NB * NB + sub * 1024);
    float4 j = __ldcg(&j4[tid]);
    float sj = (j.x + j.y) + (j.z + j.w);
    float ej = j.x * __log2f(j.x + EPS)
             + j.y * __log2f(j.y + EPS)
             + j.z * __log2f(j.z + EPS)
             + j.w * __log2f(j.w + EPS);
    j4[tid] = make_float4(0.0f, 0.0f, 0.0f, 0.0f);   // re-zero for next replay

    sj = fred256(sj, sred);
    ej = fred256(ej, sred);
    if (tid == 0) {
        atomicAdd(&g_sj[b], (double)sj);
        atomicAdd(&g_ej[b], (double)ej);
    }

    // marginals: exact reference math, one CTA per batch
    if (sub == 0) {
        float h1 = __ldcg(&g_h1[b * NB + tid]);
        float h2 = __ldcg(&g_h2[b * NB + tid]);
        g_h1[b * NB + tid] = 0.0f;                    // re-zero
        g_h2[b * NB + tid] = 0.0f;
        float m1 = h1 * INV_N;
        float m2 = h2 * INV_N;
        float S1 = fred256(m1, sred);
        float S2 = fred256(m2, sred);
        float p1 = m1 / (S1 + EPS);
        float p2 = m2 / (S2 + EPS);
        float e1 = fred256(p1 * __log2f(p1 + EPS), sred);
        float e2 = fred256(p2 * __log2f(p2 + EPS), sred);
        if (tid == 0) { g_H1[b] = -e1; g_H2[b] = -e2; }
    }

    // ================= two-level completion =================
    __threadfence();
    __syncthreads();
    if (tid == 0) {
        unsigned t = atomicAdd(&g_bar2[b], 1u);
        if (t == (unsigned)(CPB - 1)) {
            // batch finalizer: all 64 CTAs of this batch done
            __threadfence();
            double Sj = g_sj[b];
            double Ej = g_ej[b];
            double den = Sj + (double)EPS;
            // Hj = -sum q*log2(q+eps), q=j/(Sj+eps), single-pass factored
            double Hj = -(Ej - Sj * log2(den)) / den;
            double H1 = (double)g_H1[b];
            double H2 = (double)g_H2[b];
            g_mi[b] = (float)(2.0 * (H1 + H2 - Hj) / (H1 + H2));
            // reset per-batch state for next replay (all 64 passed the polls)
            g_sj[b] = 0.0; g_ej[b] = 0.0;
            g_barA[b] = 0u; g_bar2[b] = 0u;
            __threadfence();
            unsigned d = atomicAdd(&g_done, 1u);
            if (d == (unsigned)(NBATCH - 1)) {
                __threadfence();
                out[0] = 0.25f * (g_mi[0] + g_mi[1] + g_mi[2] + g_mi[3]);
                g_done = 0u;
            }
        }
    }
}

extern "C" void kernel_launch(void* const* d_in, const int* in_sizes, int n_in,
                              void* d_out, int out_size) {
    const float* in1 = (const float*)d_in[0];
    const float* in2 = (const float*)d_in[1];
    mi_fused_kernel<<<GRID, TPB>>>(in1, in2, (float*)d_out);
}

// round 6
// speedup vs baseline: 1.1098x; 1.1098x over previous
#include <cuda_runtime.h>
#include <math.h>

#define NB     256
#define NPB    65536
#define NBATCH 4
#define EPS    1e-10f
#define INV_N  (1.0f / 65536.0f)
#define RREP   8              // marginal replication factor

// ---------- persistent scratch (zero-init at load; re-zeroed every call) ----------
// Slot-shifted joint: J2[b][i][j][0] feeds cell (i,j), J2[b][i][j][1] feeds cell (i,j+1).
__device__ float  g_J2[NBATCH][NB][NB][2];          // 2 MB
__device__ float  g_M1[NBATCH][RREP][NB][2];        // 64 KB, slot-shifted marginals
__device__ float  g_M2[NBATCH][RREP][NB][2];
__device__ double g_sj[NBATCH];
__device__ double g_ej[NBATCH];
__device__ float  g_H1[NBATCH], g_H2[NBATCH];
__device__ unsigned g_bar1;

__device__ __forceinline__ void red2(float* p, float a, float b) {
    asm volatile("red.global.add.v2.f32 [%0], {%1, %2};"
                 :: "l"(p), "f"(a), "f"(b) : "memory");
}

// ================= kernel 1: sparse KDE accumulation =================
// sigma=0.1 in bin units: only the two straddling bins carry weight
// (third bin is <= e^-50 ~ 2e-22 relative). All accumulation is vector
// red.v2.f32 into slot-shifted layouts -> 4 LSU ops per pixel, no smem.
#define THREADS_ACC 256
#define PIX_PER_CTA 1024

__global__ __launch_bounds__(THREADS_ACC)
void mi_accum_kernel(const float* __restrict__ in1, const float* __restrict__ in2) {
    int tid = threadIdx.x;
    int blk = blockIdx.x;
    int base = blk * PIX_PER_CTA;
    int b = base >> 16;                 // batch
    int r = blk & (RREP - 1);           // marginal replica

    float4 a = ((const float4*)(in1 + base))[tid];
    float4 c = ((const float4*)(in2 + base))[tid];
    const float xs1[4] = {a.x, a.y, a.z, a.w};
    const float xs2[4] = {c.x, c.y, c.z, c.w};

#pragma unroll
    for (int k = 0; k < 4; k++) {
        float x1 = xs1[k] * 255.0f;
        float x2 = xs2[k] * 255.0f;
        int i0 = min((int)floorf(x1), NB - 2);
        int j0 = min((int)floorf(x2), NB - 2);
        float f1 = x1 - (float)i0, q1 = 1.0f - f1;
        float f2 = x2 - (float)j0, q2 = 1.0f - f2;
        float wa1 = __expf(-50.0f * f1 * f1);
        float wb1 = __expf(-50.0f * q1 * q1);
        float wa2 = __expf(-50.0f * f2 * f2);
        float wb2 = __expf(-50.0f * q2 * q2);

        red2(&g_J2[b][i0][j0][0],     wa1 * wa2, wa1 * wb2);
        red2(&g_J2[b][i0 + 1][j0][0], wb1 * wa2, wb1 * wb2);
        red2(&g_M1[b][r][i0][0], wa1, wb1);
        red2(&g_M2[b][r][j0][0], wa2, wb2);
    }
}

// ================= kernel 2: fold + reduce + combine + re-zero =================
__device__ __forceinline__ float fred256(float v, float* sred) {
#pragma unroll
    for (int o = 16; o; o >>= 1) v += __shfl_xor_sync(0xffffffffu, v, o);
    int wid = threadIdx.x >> 5, lid = threadIdx.x & 31;
    if (lid == 0) sred[wid] = v;
    __syncthreads();
    float rr = 0.0f;
    if (threadIdx.x < 32) {
        rr = (threadIdx.x < 8) ? sred[threadIdx.x] : 0.0f;
#pragma unroll
        for (int o = 4; o; o >>= 1) rr += __shfl_xor_sync(0xffffffffu, rr, o);
        if (threadIdx.x == 0) sred[0] = rr;
    }
    __syncthreads();
    float out = sred[0];
    __syncthreads();
    return out;
}

// 256 CTAs x 256 thr. CTA (rb=blk/64, sub=blk%64) folds rows [4*sub..4*sub+3]
// of batch rb's J2 (each thread: 4 cells = 8 floats + 1 boundary scalar),
// accumulates sum and sum v*log2(v+eps), re-zeros. sub==0 also folds the
// marginals and computes exact marginal entropies. Last CTA combines.
__global__ __launch_bounds__(256)
void mi_reduce_final_kernel(float* __restrict__ out) {
    __shared__ float sred[8];
    int tid = threadIdx.x;
    int rb  = blockIdx.x >> 6;
    int sub = blockIdx.x & 63;

    int row   = 4 * sub + (tid >> 6);        // J2 row (i)
    int cell0 = (tid & 63) * 4;              // first cell (j) of this thread
    float* rowp = &g_J2[rb][row][0][0];      // 512 floats per row

    float4 p0 = *(float4*)(rowp + cell0 * 2);        // cells c0, c0+1 (both slots)
    float4 p1 = *(float4*)(rowp + cell0 * 2 + 4);    // cells c0+2, c0+3
    float prev = (cell0 == 0) ? 0.0f : rowp[cell0 * 2 - 1];   // [c0-1][1]

    float v0 = p0.x + prev;
    float v1 = p0.z + p0.y;
    float v2 = p1.x + p0.w;
    float v3 = p1.z + p1.y;                  // p1.w feeds next thread's v0

    float sj = (v0 + v1) + (v2 + v3);
    float ej = v0 * __log2f(v0 + EPS)
             + v1 * __log2f(v1 + EPS)
             + v2 * __log2f(v2 + EPS)
             + v3 * __log2f(v3 + EPS);

    // re-zero for next replay (each thread zeros exactly its 8 floats)
    *(float4*)(rowp + cell0 * 2)     = make_float4(0.f, 0.f, 0.f, 0.f);
    *(float4*)(rowp + cell0 * 2 + 4) = make_float4(0.f, 0.f, 0.f, 0.f);

    sj = fred256(sj, sred);
    ej = fred256(ej, sred);
    if (tid == 0) {
        atomicAdd(&g_sj[rb], (double)sj);
        atomicAdd(&g_ej[rb], (double)ej);
    }

    // marginals: fold replicas + slot shift, exact reference entropy math
    if (sub == 0) {
        float h1 = 0.0f, h2 = 0.0f;
#pragma unroll
        for (int r = 0; r < RREP; r++) {
            float2 m1 = *(float2*)&g_M1[rb][r][tid][0];
            float2 m2 = *(float2*)&g_M2[rb][r][tid][0];
            h1 += m1.x;  h2 += m2.x;
            if (tid > 0) {
                h1 += g_M1[rb][r][tid - 1][1];
                h2 += g_M2[rb][r][tid - 1][1];
            }
            *(float2*)&g_M1[rb][r][tid][0] = make_float2(0.f, 0.f);   // re-zero
            *(float2*)&g_M2[rb][r][tid][0] = make_float2(0.f, 0.f);
        }
        float m1 = h1 * INV_N;
        float m2 = h2 * INV_N;
        float S1 = fred256(m1, sred);
        float S2 = fred256(m2, sred);
        float p1v = m1 / (S1 + EPS);
        float p2v = m2 / (S2 + EPS);
        float e1 = fred256(p1v * __log2f(p1v + EPS), sred);
        float e2 = fred256(p2v * __log2f(p2v + EPS), sred);
        if (tid == 0) { g_H1[rb] = -e1; g_H2[rb] = -e2; }
    }

    // last-block combine + reset
    __threadfence();
    __syncthreads();
    if (tid == 0) {
        unsigned t = atomicAdd(&g_bar1, 1u);
        if (t == 255u) {
            __threadfence();
            double acc = 0.0;
#pragma unroll
            for (int bb = 0; bb < NBATCH; bb++) {
                double Sj = g_sj[bb];
                double Ej = g_ej[bb];
                double den = Sj + (double)EPS;
                // Hj = -sum q*log2(q+eps), q=j/(Sj+eps), factored single-pass
                double Hj = -(Ej - Sj * log2(den)) / den;
                double H1 = (double)g_H1[bb];
                double H2 = (double)g_H2[bb];
                acc += 2.0 * (H1 + H2 - Hj) / (H1 + H2);
                g_sj[bb] = 0.0; g_ej[bb] = 0.0;
                g_H1[bb] = 0.0f; g_H2[bb] = 0.0f;
            }
            out[0] = (float)(acc * 0.25);
            g_bar1 = 0u;
        }
    }
}

// ================= launch: 2 kernels =================
extern "C" void kernel_launch(void* const* d_in, const int* in_sizes, int n_in,
                              void* d_out, int out_size) {
    const float* in1 = (const float*)d_in[0];
    const float* in2 = (const float*)d_in[1];
    float* out = (float*)d_out;

    mi_accum_kernel<<<(NBATCH * NPB) / PIX_PER_CTA, THREADS_ACC>>>(in1, in2);
    mi_reduce_final_kernel<<<256, 256>>>(out);
}

// round 7
// speedup vs baseline: 1.2750x; 1.1488x over previous
#include <cuda_runtime.h>
#include <math.h>

#define NB     256
#define NPB    65536
#define NBATCH 4
#define EPS    1e-10f
#define INV_N  (1.0f / 65536.0f)

// ---------- persistent scratch (zero-init at load; re-zeroed every call) ----------
// Slot-shifted joint: J2[b][i][j][0] feeds cell (i,j), J2[b][i][j][1] feeds (i,j+1).
__device__ float  g_J2[NBATCH][NB][NB][2];     // 2 MB
__device__ float  g_h1[NBATCH * NB];
__device__ float  g_h2[NBATCH * NB];
__device__ double g_sj[NBATCH];
__device__ double g_ej[NBATCH];
__device__ float  g_H1[NBATCH], g_H2[NBATCH];
__device__ unsigned g_bar1;

__device__ __forceinline__ void red2(float* p, float a, float b) {
    asm volatile("red.global.add.v2.f32 [%0], {%1, %2};"
                 :: "l"(p), "f"(a), "f"(b) : "memory");
}

// ================= kernel 1: sparse KDE accumulation =================
// sigma=0.1 in bin units: only the two straddling bins carry weight (third
// bin is <= e^-50 ~ 2e-22 relative). Joint: 2 aligned red.v2 per pixel into
// the slot-shifted layout. Marginals: shared-memory atomics (cheap ATOMS,
// avoids divergent-address REDG wavefronts).
#define THREADS_ACC 256
#define PIX_PER_CTA 1024

__global__ __launch_bounds__(THREADS_ACC)
void mi_accum_kernel(const float* __restrict__ in1, const float* __restrict__ in2) {
    __shared__ float sh1[NB];
    __shared__ float sh2[NB];
    int tid = threadIdx.x;
    int base = blockIdx.x * PIX_PER_CTA;
    int b = base >> 16;

    float4 a = ((const float4*)(in1 + base))[tid];
    float4 c = ((const float4*)(in2 + base))[tid];

    sh1[tid] = 0.0f;
    sh2[tid] = 0.0f;
    __syncthreads();

    const float xs1[4] = {a.x, a.y, a.z, a.w};
    const float xs2[4] = {c.x, c.y, c.z, c.w};

#pragma unroll
    for (int k = 0; k < 4; k++) {
        float x1 = xs1[k] * 255.0f;
        float x2 = xs2[k] * 255.0f;
        int i0 = min((int)floorf(x1), NB - 2);
        int j0 = min((int)floorf(x2), NB - 2);
        float f1 = x1 - (float)i0, q1 = 1.0f - f1;
        float f2 = x2 - (float)j0, q2 = 1.0f - f2;
        float wa1 = __expf(-50.0f * f1 * f1);
        float wb1 = __expf(-50.0f * q1 * q1);
        float wa2 = __expf(-50.0f * f2 * f2);
        float wb2 = __expf(-50.0f * q2 * q2);

        red2(&g_J2[b][i0][j0][0],     wa1 * wa2, wa1 * wb2);
        red2(&g_J2[b][i0 + 1][j0][0], wb1 * wa2, wb1 * wb2);

        atomicAdd(&sh1[i0],     wa1);
        atomicAdd(&sh1[i0 + 1], wb1);
        atomicAdd(&sh2[j0],     wa2);
        atomicAdd(&sh2[j0 + 1], wb2);
    }

    __syncthreads();
    atomicAdd(&g_h1[b * NB + tid], sh1[tid]);
    atomicAdd(&g_h2[b * NB + tid], sh2[tid]);
}

// ================= kernel 2: fold + reduce + combine + re-zero =================
__device__ __forceinline__ float fred256(float v, float* sred) {
#pragma unroll
    for (int o = 16; o; o >>= 1) v += __shfl_xor_sync(0xffffffffu, v, o);
    int wid = threadIdx.x >> 5, lid = threadIdx.x & 31;
    if (lid == 0) sred[wid] = v;
    __syncthreads();
    float rr = 0.0f;
    if (threadIdx.x < 32) {
        rr = (threadIdx.x < 8) ? sred[threadIdx.x] : 0.0f;
#pragma unroll
        for (int o = 4; o; o >>= 1) rr += __shfl_xor_sync(0xffffffffu, rr, o);
        if (threadIdx.x == 0) sred[0] = rr;
    }
    __syncthreads();
    float out = sred[0];
    __syncthreads();
    return out;
}

// 256 CTAs x 256 thr. CTA (rb, sub) folds rows [4*sub..4*sub+3] of batch rb.
// Each thread: 4 cells (cell j = slot[j][0] + slot[j-1][1]). All sources of a
// row live in ONE CTA, so: load everything -> __syncthreads -> zero (no race).
__global__ __launch_bounds__(256)
void mi_reduce_final_kernel(float* __restrict__ out) {
    __shared__ float sred[8];
    int tid = threadIdx.x;
    int rb  = blockIdx.x >> 6;
    int sub = blockIdx.x & 63;

    int row   = 4 * sub + (tid >> 6);
    int cell0 = (tid & 63) * 4;
    float* rowp = &g_J2[rb][row][0][0];      // 512 floats per row

    float4 p0 = *(float4*)(rowp + cell0 * 2);        // slots c0, c0+1
    float4 p1 = *(float4*)(rowp + cell0 * 2 + 4);    // slots c0+2, c0+3
    float prev = (cell0 == 0) ? 0.0f : rowp[cell0 * 2 - 1];   // [c0-1][1]

    __syncthreads();                          // all reads done before any zeroing
    *(float4*)(rowp + cell0 * 2)     = make_float4(0.f, 0.f, 0.f, 0.f);
    *(float4*)(rowp + cell0 * 2 + 4) = make_float4(0.f, 0.f, 0.f, 0.f);

    float v0 = p0.x + prev;
    float v1 = p0.z + p0.y;
    float v2 = p1.x + p0.w;
    float v3 = p1.z + p1.y;                   // p1.w feeds next thread's v0

    float sj = (v0 + v1) + (v2 + v3);
    float ej = v0 * __log2f(v0 + EPS)
             + v1 * __log2f(v1 + EPS)
             + v2 * __log2f(v2 + EPS)
             + v3 * __log2f(v3 + EPS);

    sj = fred256(sj, sred);
    ej = fred256(ej, sred);
    if (tid == 0) {
        atomicAdd(&g_sj[rb], (double)sj);
        atomicAdd(&g_ej[rb], (double)ej);
    }

    // marginals: exact reference math, one CTA per batch
    if (sub == 0) {
        float h1 = __ldcg(&g_h1[rb * NB + tid]);
        float h2 = __ldcg(&g_h2[rb * NB + tid]);
        g_h1[rb * NB + tid] = 0.0f;           // same-thread read-then-zero: safe
        g_h2[rb * NB + tid] = 0.0f;
        float m1 = h1 * INV_N;
        float m2 = h2 * INV_N;
        float S1 = fred256(m1, sred);
        float S2 = fred256(m2, sred);
        float p1v = m1 / (S1 + EPS);
        float p2v = m2 / (S2 + EPS);
        float e1 = fred256(p1v * __log2f(p1v + EPS), sred);
        float e2 = fred256(p2v * __log2f(p2v + EPS), sred);
        if (tid == 0) { g_H1[rb] = -e1; g_H2[rb] = -e2; }
    }

    // last-block combine + reset
    __threadfence();
    __syncthreads();
    if (tid == 0) {
        unsigned t = atomicAdd(&g_bar1, 1u);
        if (t == 255u) {
            __threadfence();
            double acc = 0.0;
#pragma unroll
            for (int bb = 0; bb < NBATCH; bb++) {
                double Sj = g_sj[bb];
                double Ej = g_ej[bb];
                double den = Sj + (double)EPS;
                // Hj = -sum q*log2(q+eps), q=j/(Sj+eps), factored single-pass
                double Hj = -(Ej - Sj * log2(den)) / den;
                double H1 = (double)g_H1[bb];
                double H2 = (double)g_H2[bb];
                acc += 2.0 * (H1 + H2 - Hj) / (H1 + H2);
                g_sj[bb] = 0.0; g_ej[bb] = 0.0;
                g_H1[bb] = 0.0f; g_H2[bb] = 0.0f;
            }
            out[0] = (float)(acc * 0.25);
            g_bar1 = 0u;
        }
    }
}

// ================= launch: 2 kernels =================
extern "C" void kernel_launch(void* const* d_in, const int* in_sizes, int n_in,
                              void* d_out, int out_size) {
    const float* in1 = (const float*)d_in[0];
    const float* in2 = (const float*)d_in[1];
    float* out = (float*)d_out;

    mi_accum_kernel<<<(NBATCH * NPB) / PIX_PER_CTA, THREADS_ACC>>>(in1, in2);
    mi_reduce_final_kernel<<<256, 256>>>(out);
}